// round 10
// baseline (speedup 1.0000x reference)
#include <cuda_runtime.h>
#include <cuda_bf16.h>
#include <cstdint>

// CenterLoss: out = mean_i ||x_i - centers[labels_i]||^2
// (clamp [1e-12,1e12] dropped: per-row dist ~2D~4096, clamp effect <1e-12/B.)
//
// R9: column-blocked. CTA = (col-block cb of 32 columns, row-group of B/4 rows).
// Smem holds centers[:, cb] (C*32 floats = 96KB) + the row-group's labels.
// x is streamed in natural order, one 128-B line per warp-row, each line read
// exactly once chip-wide. c L2 traffic: 132 GB -> ~25 MB, dropping total L2
// reads under the LTS cap (~11 TB/s) that bound R5/R6. DRAM becomes binding.

#define THREADS 256
#define COLS    32           // columns per block (warp: 32 lanes x 1 float)
#define RGROUPS 4            // row groups
#define UNROLL  16

__device__ int g_labels_are_i64;

__global__ void probe_and_init(const unsigned int* __restrict__ labels_words,
                               float* __restrict__ out) {
    // int64 labels (<751): every odd 32-bit word is 0. int32: essentially never.
    __shared__ int nonzero_odd;
    if (threadIdx.x == 0) { nonzero_odd = 0; out[0] = 0.0f; }
    __syncthreads();
    if (labels_words[2 * threadIdx.x + 1] != 0u) atomicOr(&nonzero_odd, 1);
    __syncthreads();
    if (threadIdx.x == 0) g_labels_are_i64 = nonzero_odd ? 0 : 1;
}

// ---------------- column-blocked main kernel -----------------------------
__global__ __launch_bounds__(THREADS, 2)
void center_loss_col(const float* __restrict__ x,
                     const unsigned int* __restrict__ labels_words,
                     const float* __restrict__ centers,
                     float* __restrict__ out,
                     int B, int D, int C, float inv_B) {
    extern __shared__ float sh[];             // [C*COLS] c-slice, [ctaRows] labels
    const int ctaRows = B / RGROUPS;
    float* sc   = sh;
    int*   slab = (int*)(sh + (size_t)C * COLS);

    const int t    = threadIdx.x;
    const int lane = t & 31;
    const int warp = t >> 5;
    const int nw   = THREADS / 32;
    const int cb   = blockIdx.x & 63;         // 64 col-blocks (D=2048/32)
    const int rg   = blockIdx.x >> 6;
    const int row0 = rg * ctaRows;
    const int is64 = g_labels_are_i64;

    // Stage this row-group's labels.
    for (int i = t; i < ctaRows; i += THREADS)
        slab[i] = (int)labels_words[(unsigned)(row0 + i) << is64];

    // Stage the centers column-slice: sc[j*32 + col] = centers[j*D + cb*32 + col].
    const int csz = C * COLS;
    for (int i = t; i < csz; i += THREADS) {
        int j = i >> 5, col = i & 31;
        sc[i] = __ldg(&centers[(size_t)j * D + cb * COLS + col]);
    }
    __syncthreads();

    // Stream x slivers. Warp w handles rows [w*rpw, (w+1)*rpw) of the group.
    const int rpw = ctaRows / nw;             // rows per warp (512 for B=16384)
    const float* __restrict__ xb =
        x + (size_t)row0 * D + cb * COLS + lane;

    float a0 = 0.f, a1 = 0.f;

    const int rend = warp * rpw + rpw;
    for (int r = warp * rpw; r < rend; r += UNROLL) {
        float xv[UNROLL];
        #pragma unroll
        for (int u = 0; u < UNROLL; u++)
            xv[u] = __ldcs(&xb[(size_t)(r + u) * D]);
        #pragma unroll
        for (int u = 0; u < UNROLL; u++) {
            int lab = slab[r + u];                    // LDS broadcast
            float cv = sc[lab * COLS + lane];         // conflict-free LDS
            float d = xv[u] - cv;
            if (u & 1) a1 = fmaf(d, d, a1);
            else       a0 = fmaf(d, d, a0);
        }
    }

    float s = a0 + a1;
    #pragma unroll
    for (int o = 16; o; o >>= 1)
        s += __shfl_xor_sync(0xffffffffu, s, o);

    __shared__ float bsum[THREADS / 32];
    if (lane == 0) bsum[warp] = s;
    __syncthreads();
    if (t == 0) {
        float tt = 0.f;
        #pragma unroll
        for (int w = 0; w < THREADS / 32; w++) tt += bsum[w];
        atomicAdd(out, tt * inv_B);
    }
}

// ---------------- fallback (R5 quarter-row streaming) --------------------
__global__ __launch_bounds__(THREADS, 5)
void center_loss_q(const float4* __restrict__ x4,
                   const int* __restrict__ lab32,
                   const float4* __restrict__ c4,
                   float* __restrict__ out,
                   int nunits, int vpr, int vq, float inv_B) {
    const int lane   = threadIdx.x & 31;
    const int warp   = blockIdx.x * (THREADS / 32) + (threadIdx.x >> 5);
    const int nwarps = gridDim.x * (THREADS / 32);
    const int lsh    = g_labels_are_i64;
    float a0 = 0.f, a1 = 0.f, a2 = 0.f, a3 = 0.f;
    for (int u = warp; u < nunits; u += nwarps) {
        const int row = u >> 2, q = u & 3;
        const int lab = lab32[row << lsh];
        const float4* xp = x4 + (size_t)row * vpr + q * vq + lane;
        const float4* cp = c4 + (size_t)lab * vpr + q * vq + lane;
        #pragma unroll
        for (int k = 0; k < 4; k++) {
            if (q * vq + lane + 32 * k >= vpr) break;
            float4 xv = __ldcs(xp + 32 * k);
            float4 cv = __ldg(cp + 32 * k);
            float d0 = xv.x - cv.x, d1 = xv.y - cv.y;
            float d2 = xv.z - cv.z, d3 = xv.w - cv.w;
            a0 = fmaf(d0, d0, a0); a1 = fmaf(d1, d1, a1);
            a2 = fmaf(d2, d2, a2); a3 = fmaf(d3, d3, a3);
        }
    }
    float s = (a0 + a1) + (a2 + a3);
    #pragma unroll
    for (int o = 16; o; o >>= 1) s += __shfl_xor_sync(0xffffffffu, s, o);
    __shared__ float bsum[THREADS / 32];
    if (lane == 0) bsum[threadIdx.x >> 5] = s;
    __syncthreads();
    if (threadIdx.x == 0) {
        float t = 0.f;
        #pragma unroll
        for (int w = 0; w < THREADS / 32; w++) t += bsum[w];
        atomicAdd(out, t * inv_B);
    }
}

extern "C" void kernel_launch(void* const* d_in, const int* in_sizes, int n_in,
                              void* d_out, int out_size) {
    const float* x       = (const float*)d_in[0];
    const void*  labels  = d_in[1];
    const float* centers = (const float*)d_in[2];
    float*       out     = (float*)d_out;

    const int B   = in_sizes[1];
    const int D   = in_sizes[0] / B;
    const int C   = in_sizes[2] / D;
    const int vpr = D >> 2;
    const float inv_B = 1.0f / (float)B;

    probe_and_init<<<1, 256>>>((const unsigned int*)labels, out);

    const int ctaRows = B / RGROUPS;
    const size_t smem = (size_t)C * COLS * 4 + (size_t)ctaRows * 4;
    const bool col_ok = (D == 64 * COLS) &&
                        (B % (RGROUPS * (THREADS / 32) * UNROLL) == 0) &&
                        (smem <= 113 * 1024);

    if (col_ok) {
        cudaFuncSetAttribute(center_loss_col,
                             cudaFuncAttributeMaxDynamicSharedMemorySize,
                             (int)smem);
        center_loss_col<<<64 * RGROUPS, THREADS, smem>>>(
            x, (const unsigned int*)labels, centers, out, B, D, C, inv_B);
    } else {
        const int vq = vpr >> 2;
        center_loss_q<<<148 * 5, THREADS>>>((const float4*)x, (const int*)labels,
                                            (const float4*)centers, out,
                                            B * 4, vpr, vq, inv_B);
    }
}

// round 11
// speedup vs baseline: 1.2319x; 1.2319x over previous
#include <cuda_runtime.h>
#include <cuda_bf16.h>
#include <cstdint>

// CenterLoss: out = mean_i ||x_i - centers[labels_i]||^2
// (clamp [1e-12,1e12] dropped: per-row dist ~2D~4096, clamp effect <1e-12/B.)
//
// R10: label-scan grouping, zero prep kernels. Work item = (label j, row
// parity h), pulled via global ticket. CTA scans the L2-resident label array
// to enumerate its rows (deterministic CTA prefix-sum -> smem list), loads
// center row j ONCE into registers, then streams its x rows 4-at-a-time
// (8 LDG.128 in flight / thread-group). Kills the 134 GB of c L2 traffic
// that pinned R5/R6 at the ~11.3 TB/s LTS cap; DRAM becomes binding.

#define THREADS 256
#define NWARP   (THREADS / 32)
#define CAP     2048          // smem row-list capacity per chunk

__device__ int g_labels_are_i64;
__device__ int d_ticket;

// ---- init: probe label dtype, zero out + ticket -------------------------
__global__ void probe_and_init(const unsigned int* __restrict__ labels_words,
                               float* __restrict__ out) {
    __shared__ int nonzero_odd;
    if (threadIdx.x == 0) { nonzero_odd = 0; out[0] = 0.0f; d_ticket = 0; }
    __syncthreads();
    if (labels_words[2 * threadIdx.x + 1] != 0u) atomicOr(&nonzero_odd, 1);
    __syncthreads();
    if (threadIdx.x == 0) g_labels_are_i64 = nonzero_odd ? 0 : 1;
}

// ---- main: label-scan grouped kernel (D==2048 path) ---------------------
__global__ __launch_bounds__(THREADS, 4)
void center_loss_scan(const float4* __restrict__ x4,
                      const unsigned int* __restrict__ labw,
                      const float4* __restrict__ c4,
                      float* __restrict__ out,
                      int B, int vpr, int ntasks, float inv_B) {
    __shared__ int   rowlist[CAP];
    __shared__ int   wsum[NWARP], woff[NWARP];
    __shared__ int   sh_g, sh_m;
    __shared__ float bsum[NWARP];

    const int t     = threadIdx.x;
    const int lane  = t & 31;
    const int w     = t >> 5;
    const int is64  = g_labels_are_i64;
    const int iters = (B >> 1) / THREADS;     // rows of one parity per thread

    float a0 = 0.f, a1 = 0.f, a2 = 0.f, a3 = 0.f;

    for (;;) {
        if (t == 0) sh_g = atomicAdd(&d_ticket, 1);
        __syncthreads();
        const int g = sh_g;
        if (g >= ntasks) break;
        const int j = g >> 1;
        const int h = g & 1;

        // center row j -> registers (8 KB across the CTA, L2-resident)
        const float4* __restrict__ cr = c4 + (size_t)j * vpr;
        const float4 c0 = __ldg(cr + t);
        const float4 c1 = __ldg(cr + 256 + t);

        // pass 1: count my matches among rows r = h + 2*(t + i*256)
        int cnt = 0;
        for (int i = 0; i < iters; i++) {
            int r = h + 2 * (t + i * THREADS);
            int lab = (int)__ldg(&labw[(unsigned)r << is64]);
            cnt += (lab == j);
        }
        // CTA exclusive scan of cnt
        int inc = cnt;
        #pragma unroll
        for (int o = 1; o < 32; o <<= 1) {
            int v = __shfl_up_sync(0xffffffffu, inc, o);
            if (lane >= o) inc += v;
        }
        if (lane == 31) wsum[w] = inc;
        __syncthreads();
        if (t == 0) {
            int acc = 0;
            #pragma unroll
            for (int k = 0; k < NWARP; k++) { woff[k] = acc; acc += wsum[k]; }
            sh_m = acc;
        }
        __syncthreads();
        const int off_t = woff[w] + inc - cnt;
        const int m_tot = sh_m;

        // pass 2 (chunked): build row list, process 4 rows per step
        for (int base = 0; base < m_tot; base += CAP) {
            int pos = off_t;
            for (int i = 0; i < iters; i++) {
                int r = h + 2 * (t + i * THREADS);
                int lab = (int)__ldg(&labw[(unsigned)r << is64]);
                if (lab == j) {
                    if (pos >= base && pos < base + CAP)
                        rowlist[pos - base] = r;
                    pos++;
                }
            }
            __syncthreads();
            const int mm = (m_tot - base < CAP) ? (m_tot - base) : CAP;

            int i = 0;
            for (; i + 4 <= mm; i += 4) {
                const float4* p0 = x4 + (size_t)rowlist[i]     * vpr;
                const float4* p1 = x4 + (size_t)rowlist[i + 1] * vpr;
                const float4* p2 = x4 + (size_t)rowlist[i + 2] * vpr;
                const float4* p3 = x4 + (size_t)rowlist[i + 3] * vpr;
                float4 v00 = __ldcs(p0 + t);
                float4 v01 = __ldcs(p0 + 256 + t);
                float4 v10 = __ldcs(p1 + t);
                float4 v11 = __ldcs(p1 + 256 + t);
                float4 v20 = __ldcs(p2 + t);
                float4 v21 = __ldcs(p2 + 256 + t);
                float4 v30 = __ldcs(p3 + t);
                float4 v31 = __ldcs(p3 + 256 + t);
                float d;
                d = v00.x - c0.x; a0 = fmaf(d, d, a0);
                d = v00.y - c0.y; a1 = fmaf(d, d, a1);
                d = v00.z - c0.z; a2 = fmaf(d, d, a2);
                d = v00.w - c0.w; a3 = fmaf(d, d, a3);
                d = v01.x - c1.x; a0 = fmaf(d, d, a0);
                d = v01.y - c1.y; a1 = fmaf(d, d, a1);
                d = v01.z - c1.z; a2 = fmaf(d, d, a2);
                d = v01.w - c1.w; a3 = fmaf(d, d, a3);
                d = v10.x - c0.x; a0 = fmaf(d, d, a0);
                d = v10.y - c0.y; a1 = fmaf(d, d, a1);
                d = v10.z - c0.z; a2 = fmaf(d, d, a2);
                d = v10.w - c0.w; a3 = fmaf(d, d, a3);
                d = v11.x - c1.x; a0 = fmaf(d, d, a0);
                d = v11.y - c1.y; a1 = fmaf(d, d, a1);
                d = v11.z - c1.z; a2 = fmaf(d, d, a2);
                d = v11.w - c1.w; a3 = fmaf(d, d, a3);
                d = v20.x - c0.x; a0 = fmaf(d, d, a0);
                d = v20.y - c0.y; a1 = fmaf(d, d, a1);
                d = v20.z - c0.z; a2 = fmaf(d, d, a2);
                d = v20.w - c0.w; a3 = fmaf(d, d, a3);
                d = v21.x - c1.x; a0 = fmaf(d, d, a0);
                d = v21.y - c1.y; a1 = fmaf(d, d, a1);
                d = v21.z - c1.z; a2 = fmaf(d, d, a2);
                d = v21.w - c1.w; a3 = fmaf(d, d, a3);
                d = v30.x - c0.x; a0 = fmaf(d, d, a0);
                d = v30.y - c0.y; a1 = fmaf(d, d, a1);
                d = v30.z - c0.z; a2 = fmaf(d, d, a2);
                d = v30.w - c0.w; a3 = fmaf(d, d, a3);
                d = v31.x - c1.x; a0 = fmaf(d, d, a0);
                d = v31.y - c1.y; a1 = fmaf(d, d, a1);
                d = v31.z - c1.z; a2 = fmaf(d, d, a2);
                d = v31.w - c1.w; a3 = fmaf(d, d, a3);
            }
            for (; i < mm; i++) {
                const float4* p0 = x4 + (size_t)rowlist[i] * vpr;
                float4 v00 = __ldcs(p0 + t);
                float4 v01 = __ldcs(p0 + 256 + t);
                float d;
                d = v00.x - c0.x; a0 = fmaf(d, d, a0);
                d = v00.y - c0.y; a1 = fmaf(d, d, a1);
                d = v00.z - c0.z; a2 = fmaf(d, d, a2);
                d = v00.w - c0.w; a3 = fmaf(d, d, a3);
                d = v01.x - c1.x; a0 = fmaf(d, d, a0);
                d = v01.y - c1.y; a1 = fmaf(d, d, a1);
                d = v01.z - c1.z; a2 = fmaf(d, d, a2);
                d = v01.w - c1.w; a3 = fmaf(d, d, a3);
            }
            __syncthreads();
        }
        __syncthreads();
    }

    // final reduce: warp shfl -> smem -> one atomic per CTA
    float s = (a0 + a1) + (a2 + a3);
    #pragma unroll
    for (int o = 16; o; o >>= 1)
        s += __shfl_xor_sync(0xffffffffu, s, o);
    if (lane == 0) bsum[w] = s;
    __syncthreads();
    if (t == 0) {
        float tt = 0.f;
        #pragma unroll
        for (int k = 0; k < NWARP; k++) tt += bsum[k];
        atomicAdd(out, tt * inv_B);
    }
}

// ---- fallback (R5 quarter-row streaming) --------------------------------
__global__ __launch_bounds__(THREADS, 5)
void center_loss_q(const float4* __restrict__ x4,
                   const int* __restrict__ lab32,
                   const float4* __restrict__ c4,
                   float* __restrict__ out,
                   int nunits, int vpr, int vq, float inv_B) {
    const int lane   = threadIdx.x & 31;
    const int warp   = blockIdx.x * (THREADS / 32) + (threadIdx.x >> 5);
    const int nwarps = gridDim.x * (THREADS / 32);
    const int lsh    = g_labels_are_i64;
    float a0 = 0.f, a1 = 0.f, a2 = 0.f, a3 = 0.f;
    for (int u = warp; u < nunits; u += nwarps) {
        const int row = u >> 2, q = u & 3;
        const int lab = lab32[row << lsh];
        const float4* xp = x4 + (size_t)row * vpr + q * vq + lane;
        const float4* cp = c4 + (size_t)lab * vpr + q * vq + lane;
        #pragma unroll
        for (int k = 0; k < 4; k++) {
            if (q * vq + lane + 32 * k >= vpr) break;
            float4 xv = __ldcs(xp + 32 * k);
            float4 cv = __ldg(cp + 32 * k);
            float d0 = xv.x - cv.x, d1 = xv.y - cv.y;
            float d2 = xv.z - cv.z, d3 = xv.w - cv.w;
            a0 = fmaf(d0, d0, a0); a1 = fmaf(d1, d1, a1);
            a2 = fmaf(d2, d2, a2); a3 = fmaf(d3, d3, a3);
        }
    }
    float s = (a0 + a1) + (a2 + a3);
    #pragma unroll
    for (int o = 16; o; o >>= 1) s += __shfl_xor_sync(0xffffffffu, s, o);
    __shared__ float bsum[THREADS / 32];
    if (lane == 0) bsum[threadIdx.x >> 5] = s;
    __syncthreads();
    if (threadIdx.x == 0) {
        float t = 0.f;
        #pragma unroll
        for (int w = 0; w < THREADS / 32; w++) t += bsum[w];
        atomicAdd(out, t * inv_B);
    }
}

extern "C" void kernel_launch(void* const* d_in, const int* in_sizes, int n_in,
                              void* d_out, int out_size) {
    const float* x       = (const float*)d_in[0];
    const void*  labels  = d_in[1];
    const float* centers = (const float*)d_in[2];
    float*       out     = (float*)d_out;

    const int B   = in_sizes[1];
    const int D   = in_sizes[0] / B;
    const int C   = in_sizes[2] / D;
    const int vpr = D >> 2;
    const float inv_B = 1.0f / (float)B;

    probe_and_init<<<1, 256>>>((const unsigned int*)labels, out);

    if (D == 2048 && (B % (2 * THREADS)) == 0 && B >= 2 * THREADS) {
        center_loss_scan<<<148 * 4, THREADS>>>((const float4*)x,
                                               (const unsigned int*)labels,
                                               (const float4*)centers,
                                               out, B, vpr, 2 * C, inv_B);
    } else {
        const int vq = vpr >> 2;
        center_loss_q<<<148 * 5, THREADS>>>((const float4*)x, (const int*)labels,
                                            (const float4*)centers, out,
                                            B * 4, vpr, vq, inv_B);
    }
}